// round 16
// baseline (speedup 1.0000x reference)
#include <cuda_runtime.h>
#include <cstdint>
#include <math.h>

#define BB 8
#define LLEN 1024
#define DMODEL 1024
#define NH 16
#define DHEAD 64

// ---------------- static scratch (no allocations allowed) ----------------
static __device__ float g_Q[(size_t)BB * NH * LLEN * DHEAD];
static __device__ float g_K[(size_t)BB * NH * LLEN * DHEAD];
static __device__ float g_V[(size_t)BB * NH * LLEN * DHEAD];
static __device__ float g_ctx[(size_t)BB * LLEN * DMODEL];
static __device__ float g_proj[(size_t)BB * LLEN * DMODEL];
static __device__ float g_attn[(size_t)BB * NH * LLEN * LLEN];   // fallback only
static __device__ float g_Woc[(size_t)DMODEL * DMODEL];          // tf32-rounded Wo

// ---------------- tf32 warp-MMA helpers ----------------
__device__ __forceinline__ unsigned f2tf32(float x) {
    unsigned r;
    asm("cvt.rna.tf32.f32 %0, %1;" : "=r"(r) : "f"(x));
    return r;
}
__device__ __forceinline__ float tf32f(float x) {
    return __uint_as_float(f2tf32(x));
}

__device__ __forceinline__ void mma_tf32(float* d, const unsigned* a, const unsigned* b) {
    asm volatile(
        "mma.sync.aligned.m16n8k8.row.col.f32.tf32.tf32.f32 "
        "{%0,%1,%2,%3}, {%4,%5,%6,%7}, {%8,%9}, {%0,%1,%2,%3};\n"
        : "+f"(d[0]), "+f"(d[1]), "+f"(d[2]), "+f"(d[3])
        : "r"(a[0]), "r"(a[1]), "r"(a[2]), "r"(a[3]), "r"(b[0]), "r"(b[1]));
}

__device__ __forceinline__ void cp16(void* smem_dst, const void* gsrc) {
    unsigned s = (unsigned)__cvta_generic_to_shared(smem_dst);
    asm volatile("cp.async.ca.shared.global [%0], [%1], 16;\n" :: "r"(s), "l"(gsrc));
}
__device__ __forceinline__ void cp_commit() {
    asm volatile("cp.async.commit_group;\n");
}
template <int N>
__device__ __forceinline__ void cp_wait() {
    asm volatile("cp.async.wait_group %0;\n" :: "n"(N));
}

// =========================================================================
// Kernel 0: convert only Wo (4MB) to tf32 bits — proj stays CVT-free.
// =========================================================================
__global__ void prep_wo_kernel(const float* __restrict__ Wo)
{
    const size_t N4 = (size_t)DMODEL * DMODEL / 4;
    for (size_t i = (size_t)blockIdx.x * blockDim.x + threadIdx.x;
         i < N4; i += (size_t)gridDim.x * blockDim.x) {
        float4 v = ((const float4*)Wo)[i];
        v.x = tf32f(v.x); v.y = tf32f(v.y); v.z = tf32f(v.z); v.w = tf32f(v.w);
        ((float4*)g_Woc)[i] = v;
    }
}

// =========================================================================
// Kernel 1: fused QKV projection, cp.async 2-stage, BK=16, 2 CTAs/SM
// (R13 version).
// =========================================================================
__global__ __launch_bounds__(256, 2) void qkv_mma_kernel(
    const float* __restrict__ X,
    const float* __restrict__ Wq,
    const float* __restrict__ Wk,
    const float* __restrict__ Wv)
{
    __shared__ float As[2][128][20];
    __shared__ float Bs[2][16][136];

    const int tid  = threadIdx.x;
    const int warp = tid >> 5, lane = tid & 31;
    const int wm = warp >> 1, wn = warp & 1;
    const int g = lane >> 2, t = lane & 3;

    const int m0 = blockIdx.y * 128;
    const int ng = blockIdx.x * 128;
    const int wsel = ng >> 10;
    const int nl = ng & 1023;
    const float* __restrict__ W = (wsel == 0) ? Wq : (wsel == 1 ? Wk : Wv);

    const int am0 = (tid * 2) >> 2,      ach0 = ((tid * 2) & 3) * 4;
    const int am1 = (tid * 2 + 1) >> 2,  ach1 = ((tid * 2 + 1) & 3) * 4;
    const int bk0 = (tid * 2) >> 5,      bch0 = ((tid * 2) & 31) * 4;
    const int bk1 = (tid * 2 + 1) >> 5,  bch1 = ((tid * 2 + 1) & 31) * 4;

    float acc[2][8][4];
#pragma unroll
    for (int i = 0; i < 2; i++)
#pragma unroll
        for (int j = 0; j < 8; j++)
#pragma unroll
            for (int c = 0; c < 4; c++) acc[i][j][c] = 0.f;

    cp16(&As[0][am0][ach0], &X[(size_t)(m0 + am0) * DMODEL + ach0]);
    cp16(&As[0][am1][ach1], &X[(size_t)(m0 + am1) * DMODEL + ach1]);
    cp16(&Bs[0][bk0][bch0], &W[(size_t)bk0 * DMODEL + nl + bch0]);
    cp16(&Bs[0][bk1][bch1], &W[(size_t)bk1 * DMODEL + nl + bch1]);
    cp_commit();

    const int NIT = DMODEL / 16;
    for (int it = 0; it < NIT; it++) {
        const int buf = it & 1;
        if (it + 1 < NIT) {
            const int k0 = (it + 1) * 16;
            cp16(&As[buf ^ 1][am0][ach0], &X[(size_t)(m0 + am0) * DMODEL + k0 + ach0]);
            cp16(&As[buf ^ 1][am1][ach1], &X[(size_t)(m0 + am1) * DMODEL + k0 + ach1]);
            cp16(&Bs[buf ^ 1][bk0][bch0], &W[(size_t)(k0 + bk0) * DMODEL + nl + bch0]);
            cp16(&Bs[buf ^ 1][bk1][bch1], &W[(size_t)(k0 + bk1) * DMODEL + nl + bch1]);
            cp_commit();
            cp_wait<1>();
        } else {
            cp_wait<0>();
        }
        __syncthreads();

#pragma unroll
        for (int ks = 0; ks < 16; ks += 8) {
            unsigned af[2][4], bf[8][2];
#pragma unroll
            for (int i = 0; i < 2; i++) {
                int mr = wm * 32 + i * 16;
                af[i][0] = f2tf32(As[buf][mr + g][ks + t]);
                af[i][1] = f2tf32(As[buf][mr + g + 8][ks + t]);
                af[i][2] = f2tf32(As[buf][mr + g][ks + t + 4]);
                af[i][3] = f2tf32(As[buf][mr + g + 8][ks + t + 4]);
            }
#pragma unroll
            for (int j = 0; j < 8; j++) {
                int nr = wn * 64 + j * 8;
                bf[j][0] = f2tf32(Bs[buf][ks + t][nr + g]);
                bf[j][1] = f2tf32(Bs[buf][ks + t + 4][nr + g]);
            }
#pragma unroll
            for (int i = 0; i < 2; i++)
#pragma unroll
                for (int j = 0; j < 8; j++) mma_tf32(acc[i][j], af[i], bf[j]);
        }
        __syncthreads();
    }

    float* __restrict__ dst = (wsel == 0) ? g_Q : (wsel == 1 ? g_K : g_V);
#pragma unroll
    for (int i = 0; i < 2; i++) {
        int r0 = m0 + wm * 32 + i * 16 + g;
        int b = r0 >> 10, l = r0 & 1023;
#pragma unroll
        for (int j = 0; j < 8; j++) {
            int cl = nl + wn * 64 + j * 8 + 2 * t;
            int h = cl >> 6, d = cl & 63;
            size_t base = ((size_t)(b * NH + h) * LLEN);
            float2 v0 = make_float2(tf32f(acc[i][j][0]), tf32f(acc[i][j][1]));
            float2 v1 = make_float2(tf32f(acc[i][j][2]), tf32f(acc[i][j][3]));
            *(float2*)&dst[(base + l) * DHEAD + d] = v0;
            *(float2*)&dst[(base + l + 8) * DHEAD + d] = v1;
        }
    }
}

// =========================================================================
// Kernel 2: FUSED scores + mask + softmax.  R13 structure + TWO independent
// MMA accumulation chains per K block (k8 0-3 and 4-7) to double MMA ILP;
// chains summed into acc[it] (block accs start at zero, so this is exact
// up to FP reassociation of the two 32-length K halves).
// =========================================================================
__global__ __launch_bounds__(256, 2) void fused_attn_kernel(
    const int* __restrict__ mask,
    float* __restrict__ attn_ext)
{
    __shared__ float Qs[16][68];
    __shared__ float Ks[2][64][68];
    __shared__ float red[16][8];

    const int tid  = threadIdx.x;
    const int warp = tid >> 5, lane = tid & 31;
    const int g = lane >> 2, t = lane & 3;

    const int bh = blockIdx.y;
    const int b  = bh / NH;
    const int m0 = blockIdx.x * 16;
    const float* __restrict__ Q = g_Q + (size_t)bh * LLEN * DHEAD;
    const float* __restrict__ K = g_K + (size_t)bh * LLEN * DHEAD;

    {
        int m = tid >> 4, kq = (tid & 15) * 4;
        *(float4*)&Qs[m][kq] = *(const float4*)&Q[(size_t)(m0 + m) * DHEAD + kq];
    }

#pragma unroll
    for (int r = 0; r < 4; r++) {
        int c = tid + r * 256;
        int row = c >> 4, c4 = (c & 15) * 4;
        cp16(&Ks[0][row][c4], &K[(size_t)row * DHEAD + c4]);
    }
    cp_commit();
    __syncthreads();

    unsigned qf[8][4];
#pragma unroll
    for (int k8 = 0; k8 < 8; k8++) {
        const int ks = k8 * 8;
        qf[k8][0] = __float_as_uint(Qs[g][ks + t]);
        qf[k8][1] = __float_as_uint(Qs[g + 8][ks + t]);
        qf[k8][2] = __float_as_uint(Qs[g][ks + t + 4]);
        qf[k8][3] = __float_as_uint(Qs[g + 8][ks + t + 4]);
    }

    float acc[16][4];
#pragma unroll
    for (int s = 0; s < 16; s++)
#pragma unroll
        for (int c = 0; c < 4; c++) acc[s][c] = 0.f;

#pragma unroll
    for (int it = 0; it < 16; it++) {
        const int buf = it & 1;
        if (it + 1 < 16) {
            const int n0 = (it + 1) * 64;
#pragma unroll
            for (int r = 0; r < 4; r++) {
                int c = tid + r * 256;
                int row = c >> 4, c4 = (c & 15) * 4;
                cp16(&Ks[buf ^ 1][row][c4], &K[(size_t)(n0 + row) * DHEAD + c4]);
            }
            cp_commit();
            cp_wait<1>();
        } else {
            cp_wait<0>();
        }
        __syncthreads();

        const int nr = warp * 8;
        // two independent accumulation chains (double the MMA ILP)
        float ca[4] = {0.f, 0.f, 0.f, 0.f};
        float cb[4] = {0.f, 0.f, 0.f, 0.f};
#pragma unroll
        for (int k8 = 0; k8 < 4; k8++) {
            const int ksa = k8 * 8;
            const int ksb = (k8 + 4) * 8;
            unsigned ba[2], bb[2];
            ba[0] = __float_as_uint(Ks[buf][nr + g][ksa + t]);
            ba[1] = __float_as_uint(Ks[buf][nr + g][ksa + t + 4]);
            bb[0] = __float_as_uint(Ks[buf][nr + g][ksb + t]);
            bb[1] = __float_as_uint(Ks[buf][nr + g][ksb + t + 4]);
            mma_tf32(ca, qf[k8], ba);
            mma_tf32(cb, qf[k8 + 4], bb);
        }
#pragma unroll
        for (int c = 0; c < 4; c++) acc[it][c] = ca[c] + cb[c];
        __syncthreads();
    }

    const float scale = 0.125f;
    const int ql = m0 + g, qh = m0 + g + 8;
    const int* __restrict__ mrl = mask + ((size_t)b * LLEN + ql) * LLEN;
    const int* __restrict__ mrh = mask + ((size_t)b * LLEN + qh) * LLEN;

    float mxl = -3e38f, mxh = -3e38f;
#pragma unroll
    for (int s = 0; s < 16; s++) {
        const int col = s * 64 + warp * 8 + 2 * t;
        const int2 mkl = *(const int2*)&mrl[col];
        const int2 mkh = *(const int2*)&mrh[col];
        float* a = acc[s];
        a[0] = mkl.x ? -1e9f : a[0] * scale;
        a[1] = mkl.y ? -1e9f : a[1] * scale;
        a[2] = mkh.x ? -1e9f : a[2] * scale;
        a[3] = mkh.y ? -1e9f : a[3] * scale;
        mxl = fmaxf(mxl, fmaxf(a[0], a[1]));
        mxh = fmaxf(mxh, fmaxf(a[2], a[3]));
    }
    mxl = fmaxf(mxl, __shfl_xor_sync(0xffffffffu, mxl, 1));
    mxl = fmaxf(mxl, __shfl_xor_sync(0xffffffffu, mxl, 2));
    mxh = fmaxf(mxh, __shfl_xor_sync(0xffffffffu, mxh, 1));
    mxh = fmaxf(mxh, __shfl_xor_sync(0xffffffffu, mxh, 2));
    if (t == 0) { red[g][warp] = mxl; red[g + 8][warp] = mxh; }
    __syncthreads();
    float Ml = red[g][0], Mh = red[g + 8][0];
#pragma unroll
    for (int w = 1; w < 8; w++) {
        Ml = fmaxf(Ml, red[g][w]);
        Mh = fmaxf(Mh, red[g + 8][w]);
    }
    __syncthreads();

    float sl = 0.f, sh = 0.f;
#pragma unroll
    for (int s = 0; s < 16; s++) {
        float* a = acc[s];
        a[0] = __expf(a[0] - Ml);
        a[1] = __expf(a[1] - Ml);
        a[2] = __expf(a[2] - Mh);
        a[3] = __expf(a[3] - Mh);
        sl += a[0] + a[1];
        sh += a[2] + a[3];
    }
    sl += __shfl_xor_sync(0xffffffffu, sl, 1);
    sl += __shfl_xor_sync(0xffffffffu, sl, 2);
    sh += __shfl_xor_sync(0xffffffffu, sh, 1);
    sh += __shfl_xor_sync(0xffffffffu, sh, 2);
    if (t == 0) { red[g][warp] = sl; red[g + 8][warp] = sh; }
    __syncthreads();
    float Sl = 0.f, Sh = 0.f;
#pragma unroll
    for (int w = 0; w < 8; w++) { Sl += red[g][w]; Sh += red[g + 8][w]; }
    const float invl = 1.0f / Sl, invh = 1.0f / Sh;

    float* __restrict__ P = attn_ext ? attn_ext : g_attn;
    float* __restrict__ prl = P + ((size_t)bh * LLEN + ql) * LLEN;
    float* __restrict__ prh = P + ((size_t)bh * LLEN + qh) * LLEN;
#pragma unroll
    for (int s = 0; s < 16; s++) {
        const int col = s * 64 + warp * 8 + 2 * t;
        const float* a = acc[s];
        *(float2*)&prl[col] = make_float2(a[0] * invl, a[1] * invl);
        *(float2*)&prh[col] = make_float2(a[2] * invh, a[3] * invh);
    }
}

// =========================================================================
// Kernel 3: context = P @ V (R13 version, unchanged).
// =========================================================================
__global__ __launch_bounds__(256, 3) void pv_mma_kernel(const float* __restrict__ attn_ext)
{
    __shared__ float Ps[2][128][20];
    __shared__ float Vs[2][16][72];

    const int tid  = threadIdx.x;
    const int warp = tid >> 5, lane = tid & 31;
    const int wm = warp >> 1, wn = warp & 1;
    const int g = lane >> 2, t = lane & 3;

    const int bh = blockIdx.y;
    const int m0 = blockIdx.x * 128;
    const float* __restrict__ P =
        (attn_ext ? attn_ext : (const float*)g_attn) + (size_t)bh * LLEN * LLEN;
    const float* __restrict__ V = g_V + (size_t)bh * LLEN * DHEAD;

    const int prow = tid >> 2, pc4 = (tid & 3) * 4;
    const int vrow = tid >> 4, vc4 = (tid & 15) * 4;

    float acc[2][4][4];
#pragma unroll
    for (int i = 0; i < 2; i++)
#pragma unroll
        for (int j = 0; j < 4; j++)
#pragma unroll
            for (int c = 0; c < 4; c++) acc[i][j][c] = 0.f;

    {
        cp16(&Ps[0][prow][pc4],      &P[(size_t)(m0 + prow) * LLEN + pc4]);
        cp16(&Ps[0][prow + 64][pc4], &P[(size_t)(m0 + prow + 64) * LLEN + pc4]);
        cp16(&Vs[0][vrow][vc4],      &V[(size_t)vrow * DHEAD + vc4]);
        cp_commit();
    }

    const int NIT = LLEN / 16;
    for (int it = 0; it < NIT; it++) {
        const int buf = it & 1;
        if (it + 1 < NIT) {
            const int k0 = (it + 1) * 16;
            cp16(&Ps[buf ^ 1][prow][pc4],      &P[(size_t)(m0 + prow) * LLEN + k0 + pc4]);
            cp16(&Ps[buf ^ 1][prow + 64][pc4], &P[(size_t)(m0 + prow + 64) * LLEN + k0 + pc4]);
            cp16(&Vs[buf ^ 1][vrow][vc4],      &V[(size_t)(k0 + vrow) * DHEAD + vc4]);
            cp_commit();
            cp_wait<1>();
        } else {
            cp_wait<0>();
        }
        __syncthreads();

#pragma unroll
        for (int ks = 0; ks < 16; ks += 8) {
            unsigned af[2][4], bf[4][2];
#pragma unroll
            for (int i = 0; i < 2; i++) {
                int mr = wm * 32 + i * 16;
                af[i][0] = f2tf32(Ps[buf][mr + g][ks + t]);
                af[i][1] = f2tf32(Ps[buf][mr + g + 8][ks + t]);
                af[i][2] = f2tf32(Ps[buf][mr + g][ks + t + 4]);
                af[i][3] = f2tf32(Ps[buf][mr + g + 8][ks + t + 4]);
            }
#pragma unroll
            for (int j = 0; j < 4; j++) {
                int nr = wn * 32 + j * 8;
                bf[j][0] = __float_as_uint(Vs[buf][ks + t][nr + g]);
                bf[j][1] = __float_as_uint(Vs[buf][ks + t + 4][nr + g]);
            }
#pragma unroll
            for (int i = 0; i < 2; i++)
#pragma unroll
                for (int j = 0; j < 4; j++) mma_tf32(acc[i][j], af[i], bf[j]);
        }
        __syncthreads();
    }

    const int b = bh / NH, h = bh % NH;
#pragma unroll
    for (int i = 0; i < 2; i++) {
        int l0 = m0 + wm * 32 + i * 16 + g;
#pragma unroll
        for (int j = 0; j < 4; j++) {
            int d = wn * 32 + j * 8 + 2 * t;
            float2 v0 = make_float2(tf32f(acc[i][j][0]), tf32f(acc[i][j][1]));
            float2 v1 = make_float2(tf32f(acc[i][j][2]), tf32f(acc[i][j][3]));
            *(float2*)&g_ctx[((size_t)(b * LLEN + l0)) * DMODEL + h * 64 + d] = v0;
            *(float2*)&g_ctx[((size_t)(b * LLEN + l0 + 8)) * DMODEL + h * 64 + d] = v1;
        }
    }
}

// =========================================================================
// Kernel 4: output projection (R13 version, unchanged).
// =========================================================================
__global__ __launch_bounds__(256, 2) void proj_mma_kernel()
{
    __shared__ float As[2][128][20];
    __shared__ float Bs[2][16][136];

    const int tid  = threadIdx.x;
    const int warp = tid >> 5, lane = tid & 31;
    const int wm = warp >> 1, wn = warp & 1;
    const int g = lane >> 2, t = lane & 3;

    const int m0 = blockIdx.y * 128;
    const int n0 = blockIdx.x * 128;
    const float* __restrict__ Wo = g_Woc;

    const int am0 = (tid * 2) >> 2,      ach0 = ((tid * 2) & 3) * 4;
    const int am1 = (tid * 2 + 1) >> 2,  ach1 = ((tid * 2 + 1) & 3) * 4;
    const int bk0 = (tid * 2) >> 5,      bch0 = ((tid * 2) & 31) * 4;
    const int bk1 = (tid * 2 + 1) >> 5,  bch1 = ((tid * 2 + 1) & 31) * 4;

    float acc[2][8][4];
#pragma unroll
    for (int i = 0; i < 2; i++)
#pragma unroll
        for (int j = 0; j < 8; j++)
#pragma unroll
            for (int c = 0; c < 4; c++) acc[i][j][c] = 0.f;

    cp16(&As[0][am0][ach0], &g_ctx[(size_t)(m0 + am0) * DMODEL + ach0]);
    cp16(&As[0][am1][ach1], &g_ctx[(size_t)(m0 + am1) * DMODEL + ach1]);
    cp16(&Bs[0][bk0][bch0], &Wo[(size_t)bk0 * DMODEL + n0 + bch0]);
    cp16(&Bs[0][bk1][bch1], &Wo[(size_t)bk1 * DMODEL + n0 + bch1]);
    cp_commit();

    const int NIT = DMODEL / 16;
    for (int it = 0; it < NIT; it++) {
        const int buf = it & 1;
        if (it + 1 < NIT) {
            const int k0 = (it + 1) * 16;
            cp16(&As[buf ^ 1][am0][ach0], &g_ctx[(size_t)(m0 + am0) * DMODEL + k0 + ach0]);
            cp16(&As[buf ^ 1][am1][ach1], &g_ctx[(size_t)(m0 + am1) * DMODEL + k0 + ach1]);
            cp16(&Bs[buf ^ 1][bk0][bch0], &Wo[(size_t)(k0 + bk0) * DMODEL + n0 + bch0]);
            cp16(&Bs[buf ^ 1][bk1][bch1], &Wo[(size_t)(k0 + bk1) * DMODEL + n0 + bch1]);
            cp_commit();
            cp_wait<1>();
        } else {
            cp_wait<0>();
        }
        __syncthreads();

#pragma unroll
        for (int ks = 0; ks < 16; ks += 8) {
            unsigned af[2][4], bf[8][2];
#pragma unroll
            for (int i = 0; i < 2; i++) {
                int mr = wm * 32 + i * 16;
                af[i][0] = __float_as_uint(As[buf][mr + g][ks + t]);
                af[i][1] = __float_as_uint(As[buf][mr + g + 8][ks + t]);
                af[i][2] = __float_as_uint(As[buf][mr + g][ks + t + 4]);
                af[i][3] = __float_as_uint(As[buf][mr + g + 8][ks + t + 4]);
            }
#pragma unroll
            for (int j = 0; j < 8; j++) {
                int nr = wn * 64 + j * 8;
                bf[j][0] = __float_as_uint(Bs[buf][ks + t][nr + g]);
                bf[j][1] = __float_as_uint(Bs[buf][ks + t + 4][nr + g]);
            }
#pragma unroll
            for (int i = 0; i < 2; i++)
#pragma unroll
                for (int j = 0; j < 8; j++) mma_tf32(acc[i][j], af[i], bf[j]);
        }
        __syncthreads();
    }

#pragma unroll
    for (int i = 0; i < 2; i++) {
        int r0 = m0 + wm * 32 + i * 16 + g;
#pragma unroll
        for (int j = 0; j < 8; j++) {
            int c = n0 + wn * 64 + j * 8 + 2 * t;
            float2 v0 = make_float2(acc[i][j][0], acc[i][j][1]);
            float2 v1 = make_float2(acc[i][j][2], acc[i][j][3]);
            *(float2*)&g_proj[(size_t)r0 * DMODEL + c] = v0;
            *(float2*)&g_proj[(size_t)(r0 + 8) * DMODEL + c] = v1;
        }
    }
}

// =========================================================================
// Kernel 5: residual + LayerNorm (unchanged).
// =========================================================================
__global__ void ln_kernel(const float* __restrict__ X,
                          const float* __restrict__ gamma,
                          const float* __restrict__ beta,
                          float* __restrict__ out)
{
    const int row = blockIdx.x;
    const int tid = threadIdx.x;
    const float* __restrict__ pr = g_proj + (size_t)row * DMODEL;
    const float* __restrict__ xr = X + (size_t)row * DMODEL;

    float4 p = reinterpret_cast<const float4*>(pr)[tid];
    float4 x = reinterpret_cast<const float4*>(xr)[tid];
    float y0 = p.x + x.x, y1 = p.y + x.y, y2 = p.z + x.z, y3 = p.w + x.w;

    __shared__ float red[8];
    float s = y0 + y1 + y2 + y3;
#pragma unroll
    for (int o = 16; o > 0; o >>= 1) s += __shfl_xor_sync(0xffffffffu, s, o);
    if ((tid & 31) == 0) red[tid >> 5] = s;
    __syncthreads();
    float tot = red[0];
#pragma unroll
    for (int w = 1; w < 8; w++) tot += red[w];
    const float mu = tot * (1.0f / DMODEL);
    __syncthreads();

    float d0 = y0 - mu, d1 = y1 - mu, d2 = y2 - mu, d3 = y3 - mu;
    float sq = d0 * d0 + d1 * d1 + d2 * d2 + d3 * d3;
#pragma unroll
    for (int o = 16; o > 0; o >>= 1) sq += __shfl_xor_sync(0xffffffffu, sq, o);
    if ((tid & 31) == 0) red[tid >> 5] = sq;
    __syncthreads();
    float tot2 = red[0];
#pragma unroll
    for (int w = 1; w < 8; w++) tot2 += red[w];
    const float var = tot2 * (1.0f / DMODEL);
    const float inv = rsqrtf(var + 1e-6f);

    const int c = tid * 4;
    float* __restrict__ orow = out + (size_t)row * DMODEL;
    orow[c + 0] = d0 * inv * gamma[c + 0] + beta[c + 0];
    orow[c + 1] = d1 * inv * gamma[c + 1] + beta[c + 1];
    orow[c + 2] = d2 * inv * gamma[c + 2] + beta[c + 2];
    orow[c + 3] = d3 * inv * gamma[c + 3] + beta[c + 3];
}

// =========================================================================
extern "C" void kernel_launch(void* const* d_in, const int* in_sizes, int n_in,
                              void* d_out, int out_size)
{
    const float* X     = (const float*)d_in[0];
    const int*   mask  = (const int*)d_in[1];
    const float* Wq    = (const float*)d_in[2];
    const float* Wk    = (const float*)d_in[3];
    const float* Wv    = (const float*)d_in[4];
    const float* Wo    = (const float*)d_in[5];
    const float* gamma = (const float*)d_in[6];
    const float* beta  = (const float*)d_in[7];
    float* out = (float*)d_out;

    const long long LN_N   = (long long)BB * LLEN * DMODEL;
    const long long ATTN_N = (long long)BB * NH * LLEN * LLEN;
    float* attn_ptr = ((long long)out_size >= LN_N + ATTN_N) ? (out + LN_N) : nullptr;

    prep_wo_kernel<<<512, 256>>>(Wo);
    qkv_mma_kernel<<<dim3(24, 64), 256>>>(X, Wq, Wk, Wv);
    fused_attn_kernel<<<dim3(64, BB * NH), 256>>>(mask, attn_ptr);
    pv_mma_kernel<<<dim3(8, BB * NH), 256>>>(attn_ptr);
    proj_mma_kernel<<<dim3(8, 64), 256>>>();
    ln_kernel<<<BB * LLEN, 256>>>(X, gamma, beta, out);
}

// round 17
// speedup vs baseline: 1.0139x; 1.0139x over previous
#include <cuda_runtime.h>
#include <cstdint>
#include <math.h>

#define BB 8
#define LLEN 1024
#define DMODEL 1024
#define NH 16
#define DHEAD 64

// ---------------- static scratch (no allocations allowed) ----------------
static __device__ float g_Q[(size_t)BB * NH * LLEN * DHEAD];
static __device__ float g_K[(size_t)BB * NH * LLEN * DHEAD];
static __device__ float g_V[(size_t)BB * NH * LLEN * DHEAD];
static __device__ float g_ctx[(size_t)BB * LLEN * DMODEL];
static __device__ float g_proj[(size_t)BB * LLEN * DMODEL];
static __device__ float g_attn[(size_t)BB * NH * LLEN * LLEN];   // fallback only
static __device__ float g_Woc[(size_t)DMODEL * DMODEL];          // tf32-rounded Wo

// ---------------- tf32 warp-MMA helpers ----------------
__device__ __forceinline__ unsigned f2tf32(float x) {
    unsigned r;
    asm("cvt.rna.tf32.f32 %0, %1;" : "=r"(r) : "f"(x));
    return r;
}
__device__ __forceinline__ float tf32f(float x) {
    return __uint_as_float(f2tf32(x));
}

__device__ __forceinline__ void mma_tf32(float* d, const unsigned* a, const unsigned* b) {
    asm volatile(
        "mma.sync.aligned.m16n8k8.row.col.f32.tf32.tf32.f32 "
        "{%0,%1,%2,%3}, {%4,%5,%6,%7}, {%8,%9}, {%0,%1,%2,%3};\n"
        : "+f"(d[0]), "+f"(d[1]), "+f"(d[2]), "+f"(d[3])
        : "r"(a[0]), "r"(a[1]), "r"(a[2]), "r"(a[3]), "r"(b[0]), "r"(b[1]));
}

__device__ __forceinline__ void cp16(void* smem_dst, const void* gsrc) {
    unsigned s = (unsigned)__cvta_generic_to_shared(smem_dst);
    asm volatile("cp.async.ca.shared.global [%0], [%1], 16;\n" :: "r"(s), "l"(gsrc));
}
__device__ __forceinline__ void cp_commit() {
    asm volatile("cp.async.commit_group;\n");
}
template <int N>
__device__ __forceinline__ void cp_wait() {
    asm volatile("cp.async.wait_group %0;\n" :: "n"(N));
}

// =========================================================================
// Kernel 0: convert only Wo (4MB) to tf32 bits — proj stays CVT-free.
// =========================================================================
__global__ void prep_wo_kernel(const float* __restrict__ Wo)
{
    const size_t N4 = (size_t)DMODEL * DMODEL / 4;
    for (size_t i = (size_t)blockIdx.x * blockDim.x + threadIdx.x;
         i < N4; i += (size_t)gridDim.x * blockDim.x) {
        float4 v = ((const float4*)Wo)[i];
        v.x = tf32f(v.x); v.y = tf32f(v.y); v.z = tf32f(v.z); v.w = tf32f(v.w);
        ((float4*)g_Woc)[i] = v;
    }
}

// 3-stage dynamic smem for qkv/proj: per stage A[128][20] + B[16][136]
#define QSTG 4736
#define QAI(s, m, k) ((s) * QSTG + (m) * 20 + (k))
#define QBI(s, k, n) ((s) * QSTG + 2560 + (k) * 136 + (n))
#define QKV_SMEM_BYTES (3 * QSTG * 4)    // 56832 B

// =========================================================================
// Kernel 1: fused QKV projection — 3-stage pipeline, ONE sync/iter
// (wait -> sync -> MMA -> stage it+2), BK=16, 2 CTAs/SM.
// =========================================================================
__global__ __launch_bounds__(256, 2) void qkv_mma_kernel(
    const float* __restrict__ X,
    const float* __restrict__ Wq,
    const float* __restrict__ Wk,
    const float* __restrict__ Wv)
{
    extern __shared__ float sm[];

    const int tid  = threadIdx.x;
    const int warp = tid >> 5, lane = tid & 31;
    const int wm = warp >> 1, wn = warp & 1;
    const int g = lane >> 2, t = lane & 3;

    const int m0 = blockIdx.y * 128;
    const int ng = blockIdx.x * 128;
    const int wsel = ng >> 10;
    const int nl = ng & 1023;
    const float* __restrict__ W = (wsel == 0) ? Wq : (wsel == 1 ? Wk : Wv);

    const int am0 = (tid * 2) >> 2,      ach0 = ((tid * 2) & 3) * 4;
    const int am1 = (tid * 2 + 1) >> 2,  ach1 = ((tid * 2 + 1) & 3) * 4;
    const int bk0 = (tid * 2) >> 5,      bch0 = ((tid * 2) & 31) * 4;
    const int bk1 = (tid * 2 + 1) >> 5,  bch1 = ((tid * 2 + 1) & 31) * 4;

    float acc[2][8][4];
#pragma unroll
    for (int i = 0; i < 2; i++)
#pragma unroll
        for (int j = 0; j < 8; j++)
#pragma unroll
            for (int c = 0; c < 4; c++) acc[i][j][c] = 0.f;

    auto stage = [&](int s, int k0) {
        cp16(&sm[QAI(s, am0, ach0)], &X[(size_t)(m0 + am0) * DMODEL + k0 + ach0]);
        cp16(&sm[QAI(s, am1, ach1)], &X[(size_t)(m0 + am1) * DMODEL + k0 + ach1]);
        cp16(&sm[QBI(s, bk0, bch0)], &W[(size_t)(k0 + bk0) * DMODEL + nl + bch0]);
        cp16(&sm[QBI(s, bk1, bch1)], &W[(size_t)(k0 + bk1) * DMODEL + nl + bch1]);
        cp_commit();
    };

    stage(0, 0);
    stage(1, 16);

    const int NIT = DMODEL / 16;     // 64
    for (int it = 0; it < NIT; it++) {
        const int buf = it % 3;
        if (it + 1 < NIT) cp_wait<1>(); else cp_wait<0>();
        __syncthreads();   // stage 'it' visible to all; prior-iter reads done

#pragma unroll
        for (int ks = 0; ks < 16; ks += 8) {
            unsigned af[2][4], bf[8][2];
#pragma unroll
            for (int i = 0; i < 2; i++) {
                int mr = wm * 32 + i * 16;
                af[i][0] = f2tf32(sm[QAI(buf, mr + g, ks + t)]);
                af[i][1] = f2tf32(sm[QAI(buf, mr + g + 8, ks + t)]);
                af[i][2] = f2tf32(sm[QAI(buf, mr + g, ks + t + 4)]);
                af[i][3] = f2tf32(sm[QAI(buf, mr + g + 8, ks + t + 4)]);
            }
#pragma unroll
            for (int j = 0; j < 8; j++) {
                int nr = wn * 64 + j * 8;
                bf[j][0] = f2tf32(sm[QBI(buf, ks + t, nr + g)]);
                bf[j][1] = f2tf32(sm[QBI(buf, ks + t + 4, nr + g)]);
            }
#pragma unroll
            for (int i = 0; i < 2; i++)
#pragma unroll
                for (int j = 0; j < 8; j++) mma_tf32(acc[i][j], af[i], bf[j]);
        }

        if (it + 2 < NIT) stage((it + 2) % 3, (it + 2) * 16);
    }

    float* __restrict__ dst = (wsel == 0) ? g_Q : (wsel == 1 ? g_K : g_V);
#pragma unroll
    for (int i = 0; i < 2; i++) {
        int r0 = m0 + wm * 32 + i * 16 + g;
        int b = r0 >> 10, l = r0 & 1023;
#pragma unroll
        for (int j = 0; j < 8; j++) {
            int cl = nl + wn * 64 + j * 8 + 2 * t;
            int h = cl >> 6, d = cl & 63;
            size_t base = ((size_t)(b * NH + h) * LLEN);
            float2 v0 = make_float2(tf32f(acc[i][j][0]), tf32f(acc[i][j][1]));
            float2 v1 = make_float2(tf32f(acc[i][j][2]), tf32f(acc[i][j][3]));
            *(float2*)&dst[(base + l) * DHEAD + d] = v0;
            *(float2*)&dst[(base + l + 8) * DHEAD + d] = v1;
        }
    }
}

// attn 3-stage dynamic smem: Qs[16][68] | Ks[3][64][68] | red[16][8]
#define A_QS 0
#define A_KS 1088
#define A_RED (1088 + 3 * 64 * 68)
#define ATTN_SMEM_BYTES ((1088 + 3 * 64 * 68 + 128) * 4)   // 57088 B
#define KIdx(s, r, c) (A_KS + (((s) * 64 + (r)) * 68) + (c))

// =========================================================================
// Kernel 2: FUSED scores + mask + softmax — 3-stage K pipeline, ONE
// sync/iter, 64-row blocks (R13 stage size), 2 CTAs/SM.
// =========================================================================
__global__ __launch_bounds__(256, 2) void fused_attn_kernel(
    const int* __restrict__ mask,
    float* __restrict__ attn_ext)
{
    extern __shared__ float sm[];
    float* Qs  = sm + A_QS;
    float* red = sm + A_RED;

    const int tid  = threadIdx.x;
    const int warp = tid >> 5, lane = tid & 31;
    const int g = lane >> 2, t = lane & 3;

    const int bh = blockIdx.y;
    const int b  = bh / NH;
    const int m0 = blockIdx.x * 16;
    const float* __restrict__ Q = g_Q + (size_t)bh * LLEN * DHEAD;
    const float* __restrict__ K = g_K + (size_t)bh * LLEN * DHEAD;

    // stage Q strip 16x64 (raw copy; already tf32 bits)
    {
        int m = tid >> 4, kq = (tid & 15) * 4;
        *(float4*)&Qs[m * 68 + kq] = *(const float4*)&Q[(size_t)(m0 + m) * DHEAD + kq];
    }

    auto stageK = [&](int s, int n0) {
#pragma unroll
        for (int r = 0; r < 4; r++) {
            int c = tid + r * 256;
            int row = c >> 4, c4 = (c & 15) * 4;
            cp16(&sm[KIdx(s, row, c4)], &K[(size_t)(n0 + row) * DHEAD + c4]);
        }
        cp_commit();
    };

    stageK(0, 0);
    stageK(1, 64);
    __syncthreads();   // Qs visible

    unsigned qf[8][4];
#pragma unroll
    for (int k8 = 0; k8 < 8; k8++) {
        const int ks = k8 * 8;
        qf[k8][0] = __float_as_uint(Qs[g * 68 + ks + t]);
        qf[k8][1] = __float_as_uint(Qs[(g + 8) * 68 + ks + t]);
        qf[k8][2] = __float_as_uint(Qs[g * 68 + ks + t + 4]);
        qf[k8][3] = __float_as_uint(Qs[(g + 8) * 68 + ks + t + 4]);
    }

    float acc[16][4];
#pragma unroll
    for (int s = 0; s < 16; s++)
#pragma unroll
        for (int c = 0; c < 4; c++) acc[s][c] = 0.f;

#pragma unroll
    for (int it = 0; it < 16; it++) {
        const int buf = it % 3;
        if (it + 1 < 16) cp_wait<1>(); else cp_wait<0>();
        __syncthreads();

        const int nr = warp * 8;
#pragma unroll
        for (int k8 = 0; k8 < 8; k8++) {
            const int ks = k8 * 8;
            unsigned bf[2];
            bf[0] = __float_as_uint(sm[KIdx(buf, nr + g, ks + t)]);
            bf[1] = __float_as_uint(sm[KIdx(buf, nr + g, ks + t + 4)]);
            mma_tf32(acc[it], qf[k8], bf);
        }

        if (it + 2 < 16) stageK((it + 2) % 3, (it + 2) * 64);
    }

    const float scale = 0.125f;
    const int ql = m0 + g, qh = m0 + g + 8;
    const int* __restrict__ mrl = mask + ((size_t)b * LLEN + ql) * LLEN;
    const int* __restrict__ mrh = mask + ((size_t)b * LLEN + qh) * LLEN;

    float mxl = -3e38f, mxh = -3e38f;
#pragma unroll
    for (int s = 0; s < 16; s++) {
        const int col = s * 64 + warp * 8 + 2 * t;
        const int2 mkl = *(const int2*)&mrl[col];
        const int2 mkh = *(const int2*)&mrh[col];
        float* a = acc[s];
        a[0] = mkl.x ? -1e9f : a[0] * scale;
        a[1] = mkl.y ? -1e9f : a[1] * scale;
        a[2] = mkh.x ? -1e9f : a[2] * scale;
        a[3] = mkh.y ? -1e9f : a[3] * scale;
        mxl = fmaxf(mxl, fmaxf(a[0], a[1]));
        mxh = fmaxf(mxh, fmaxf(a[2], a[3]));
    }
    mxl = fmaxf(mxl, __shfl_xor_sync(0xffffffffu, mxl, 1));
    mxl = fmaxf(mxl, __shfl_xor_sync(0xffffffffu, mxl, 2));
    mxh = fmaxf(mxh, __shfl_xor_sync(0xffffffffu, mxh, 1));
    mxh = fmaxf(mxh, __shfl_xor_sync(0xffffffffu, mxh, 2));
    __syncthreads();   // all MMA smem reads done before red reuse
    if (t == 0) { red[g * 8 + warp] = mxl; red[(g + 8) * 8 + warp] = mxh; }
    __syncthreads();
    float Ml = red[g * 8], Mh = red[(g + 8) * 8];
#pragma unroll
    for (int w = 1; w < 8; w++) {
        Ml = fmaxf(Ml, red[g * 8 + w]);
        Mh = fmaxf(Mh, red[(g + 8) * 8 + w]);
    }
    __syncthreads();

    float sl = 0.f, sh = 0.f;
#pragma unroll
    for (int s = 0; s < 16; s++) {
        float* a = acc[s];
        a[0] = __expf(a[0] - Ml);
        a[1] = __expf(a[1] - Ml);
        a[2] = __expf(a[2] - Mh);
        a[3] = __expf(a[3] - Mh);
        sl += a[0] + a[1];
        sh += a[2] + a[3];
    }
    sl += __shfl_xor_sync(0xffffffffu, sl, 1);
    sl += __shfl_xor_sync(0xffffffffu, sl, 2);
    sh += __shfl_xor_sync(0xffffffffu, sh, 1);
    sh += __shfl_xor_sync(0xffffffffu, sh, 2);
    if (t == 0) { red[g * 8 + warp] = sl; red[(g + 8) * 8 + warp] = sh; }
    __syncthreads();
    float Sl = 0.f, Sh = 0.f;
#pragma unroll
    for (int w = 0; w < 8; w++) { Sl += red[g * 8 + w]; Sh += red[(g + 8) * 8 + w]; }
    const float invl = 1.0f / Sl, invh = 1.0f / Sh;

    float* __restrict__ P = attn_ext ? attn_ext : g_attn;
    float* __restrict__ prl = P + ((size_t)bh * LLEN + ql) * LLEN;
    float* __restrict__ prh = P + ((size_t)bh * LLEN + qh) * LLEN;
#pragma unroll
    for (int s = 0; s < 16; s++) {
        const int col = s * 64 + warp * 8 + 2 * t;
        const float* a = acc[s];
        *(float2*)&prl[col] = make_float2(a[0] * invl, a[1] * invl);
        *(float2*)&prh[col] = make_float2(a[2] * invh, a[3] * invh);
    }
}

// =========================================================================
// Kernel 3: context = P @ V (R13 version, unchanged — DRAM-bound plateau).
// =========================================================================
__global__ __launch_bounds__(256, 3) void pv_mma_kernel(const float* __restrict__ attn_ext)
{
    __shared__ float Ps[2][128][20];
    __shared__ float Vs[2][16][72];

    const int tid  = threadIdx.x;
    const int warp = tid >> 5, lane = tid & 31;
    const int wm = warp >> 1, wn = warp & 1;
    const int g = lane >> 2, t = lane & 3;

    const int bh = blockIdx.y;
    const int m0 = blockIdx.x * 128;
    const float* __restrict__ P =
        (attn_ext ? attn_ext : (const float*)g_attn) + (size_t)bh * LLEN * LLEN;
    const float* __restrict__ V = g_V + (size_t)bh * LLEN * DHEAD;

    const int prow = tid >> 2, pc4 = (tid & 3) * 4;
    const int vrow = tid >> 4, vc4 = (tid & 15) * 4;

    float acc[2][4][4];
#pragma unroll
    for (int i = 0; i < 2; i++)
#pragma unroll
        for (int j = 0; j < 4; j++)
#pragma unroll
            for (int c = 0; c < 4; c++) acc[i][j][c] = 0.f;

    {
        cp16(&Ps[0][prow][pc4],      &P[(size_t)(m0 + prow) * LLEN + pc4]);
        cp16(&Ps[0][prow + 64][pc4], &P[(size_t)(m0 + prow + 64) * LLEN + pc4]);
        cp16(&Vs[0][vrow][vc4],      &V[(size_t)vrow * DHEAD + vc4]);
        cp_commit();
    }

    const int NIT = LLEN / 16;
    for (int it = 0; it < NIT; it++) {
        const int buf = it & 1;
        if (it + 1 < NIT) {
            const int k0 = (it + 1) * 16;
            cp16(&Ps[buf ^ 1][prow][pc4],      &P[(size_t)(m0 + prow) * LLEN + k0 + pc4]);
            cp16(&Ps[buf ^ 1][prow + 64][pc4], &P[(size_t)(m0 + prow + 64) * LLEN + k0 + pc4]);
            cp16(&Vs[buf ^ 1][vrow][vc4],      &V[(size_t)(k0 + vrow) * DHEAD + vc4]);
            cp_commit();
            cp_wait<1>();
        } else {
            cp_wait<0>();
        }
        __syncthreads();

#pragma unroll
        for (int ks = 0; ks < 16; ks += 8) {
            unsigned af[2][4], bf[4][2];
#pragma unroll
            for (int i = 0; i < 2; i++) {
                int mr = wm * 32 + i * 16;
                af[i][0] = f2tf32(Ps[buf][mr + g][ks + t]);
                af[i][1] = f2tf32(Ps[buf][mr + g + 8][ks + t]);
                af[i][2] = f2tf32(Ps[buf][mr + g][ks + t + 4]);
                af[i][3] = f2tf32(Ps[buf][mr + g + 8][ks + t + 4]);
            }
#pragma unroll
            for (int j = 0; j < 4; j++) {
                int nr = wn * 32 + j * 8;
                bf[j][0] = __float_as_uint(Vs[buf][ks + t][nr + g]);
                bf[j][1] = __float_as_uint(Vs[buf][ks + t + 4][nr + g]);
            }
#pragma unroll
            for (int i = 0; i < 2; i++)
#pragma unroll
                for (int j = 0; j < 4; j++) mma_tf32(acc[i][j], af[i], bf[j]);
        }
        __syncthreads();
    }

    const int b = bh / NH, h = bh % NH;
#pragma unroll
    for (int i = 0; i < 2; i++) {
        int l0 = m0 + wm * 32 + i * 16 + g;
#pragma unroll
        for (int j = 0; j < 4; j++) {
            int d = wn * 32 + j * 8 + 2 * t;
            float2 v0 = make_float2(tf32f(acc[i][j][0]), tf32f(acc[i][j][1]));
            float2 v1 = make_float2(tf32f(acc[i][j][2]), tf32f(acc[i][j][3]));
            *(float2*)&g_ctx[((size_t)(b * LLEN + l0)) * DMODEL + h * 64 + d] = v0;
            *(float2*)&g_ctx[((size_t)(b * LLEN + l0 + 8)) * DMODEL + h * 64 + d] = v1;
        }
    }
}

// =========================================================================
// Kernel 4: output projection — 3-stage pipeline, ONE sync/iter, CVT-free.
// =========================================================================
__global__ __launch_bounds__(256, 2) void proj_mma_kernel()
{
    extern __shared__ float sm[];

    const int tid  = threadIdx.x;
    const int warp = tid >> 5, lane = tid & 31;
    const int wm = warp >> 1, wn = warp & 1;
    const int g = lane >> 2, t = lane & 3;

    const int m0 = blockIdx.y * 128;
    const int n0 = blockIdx.x * 128;
    const float* __restrict__ Wo = g_Woc;

    const int am0 = (tid * 2) >> 2,      ach0 = ((tid * 2) & 3) * 4;
    const int am1 = (tid * 2 + 1) >> 2,  ach1 = ((tid * 2 + 1) & 3) * 4;
    const int bk0 = (tid * 2) >> 5,      bch0 = ((tid * 2) & 31) * 4;
    const int bk1 = (tid * 2 + 1) >> 5,  bch1 = ((tid * 2 + 1) & 31) * 4;

    float acc[2][8][4];
#pragma unroll
    for (int i = 0; i < 2; i++)
#pragma unroll
        for (int j = 0; j < 8; j++)
#pragma unroll
            for (int c = 0; c < 4; c++) acc[i][j][c] = 0.f;

    auto stage = [&](int s, int k0) {
        cp16(&sm[QAI(s, am0, ach0)], &g_ctx[(size_t)(m0 + am0) * DMODEL + k0 + ach0]);
        cp16(&sm[QAI(s, am1, ach1)], &g_ctx[(size_t)(m0 + am1) * DMODEL + k0 + ach1]);
        cp16(&sm[QBI(s, bk0, bch0)], &Wo[(size_t)(k0 + bk0) * DMODEL + n0 + bch0]);
        cp16(&sm[QBI(s, bk1, bch1)], &Wo[(size_t)(k0 + bk1) * DMODEL + n0 + bch1]);
        cp_commit();
    };

    stage(0, 0);
    stage(1, 16);

    const int NIT = DMODEL / 16;
    for (int it = 0; it < NIT; it++) {
        const int buf = it % 3;
        if (it + 1 < NIT) cp_wait<1>(); else cp_wait<0>();
        __syncthreads();

#pragma unroll
        for (int ks = 0; ks < 16; ks += 8) {
            unsigned af[2][4], bf[8][2];
#pragma unroll
            for (int i = 0; i < 2; i++) {
                int mr = wm * 32 + i * 16;
                af[i][0] = __float_as_uint(sm[QAI(buf, mr + g, ks + t)]);
                af[i][1] = __float_as_uint(sm[QAI(buf, mr + g + 8, ks + t)]);
                af[i][2] = __float_as_uint(sm[QAI(buf, mr + g, ks + t + 4)]);
                af[i][3] = __float_as_uint(sm[QAI(buf, mr + g + 8, ks + t + 4)]);
            }
#pragma unroll
            for (int j = 0; j < 8; j++) {
                int nr = wn * 64 + j * 8;
                bf[j][0] = __float_as_uint(sm[QBI(buf, ks + t, nr + g)]);
                bf[j][1] = __float_as_uint(sm[QBI(buf, ks + t + 4, nr + g)]);
            }
#pragma unroll
            for (int i = 0; i < 2; i++)
#pragma unroll
                for (int j = 0; j < 8; j++) mma_tf32(acc[i][j], af[i], bf[j]);
        }

        if (it + 2 < NIT) stage((it + 2) % 3, (it + 2) * 16);
    }

#pragma unroll
    for (int i = 0; i < 2; i++) {
        int r0 = m0 + wm * 32 + i * 16 + g;
#pragma unroll
        for (int j = 0; j < 8; j++) {
            int c = n0 + wn * 64 + j * 8 + 2 * t;
            float2 v0 = make_float2(acc[i][j][0], acc[i][j][1]);
            float2 v1 = make_float2(acc[i][j][2], acc[i][j][3]);
            *(float2*)&g_proj[(size_t)r0 * DMODEL + c] = v0;
            *(float2*)&g_proj[(size_t)(r0 + 8) * DMODEL + c] = v1;
        }
    }
}

// =========================================================================
// Kernel 5: residual + LayerNorm (unchanged).
// =========================================================================
__global__ void ln_kernel(const float* __restrict__ X,
                          const float* __restrict__ gamma,
                          const float* __restrict__ beta,
                          float* __restrict__ out)
{
    const int row = blockIdx.x;
    const int tid = threadIdx.x;
    const float* __restrict__ pr = g_proj + (size_t)row * DMODEL;
    const float* __restrict__ xr = X + (size_t)row * DMODEL;

    float4 p = reinterpret_cast<const float4*>(pr)[tid];
    float4 x = reinterpret_cast<const float4*>(xr)[tid];
    float y0 = p.x + x.x, y1 = p.y + x.y, y2 = p.z + x.z, y3 = p.w + x.w;

    __shared__ float red[8];
    float s = y0 + y1 + y2 + y3;
#pragma unroll
    for (int o = 16; o > 0; o >>= 1) s += __shfl_xor_sync(0xffffffffu, s, o);
    if ((tid & 31) == 0) red[tid >> 5] = s;
    __syncthreads();
    float tot = red[0];
#pragma unroll
    for (int w = 1; w < 8; w++) tot += red[w];
    const float mu = tot * (1.0f / DMODEL);
    __syncthreads();

    float d0 = y0 - mu, d1 = y1 - mu, d2 = y2 - mu, d3 = y3 - mu;
    float sq = d0 * d0 + d1 * d1 + d2 * d2 + d3 * d3;
#pragma unroll
    for (int o = 16; o > 0; o >>= 1) sq += __shfl_xor_sync(0xffffffffu, sq, o);
    if ((tid & 31) == 0) red[tid >> 5] = sq;
    __syncthreads();
    float tot2 = red[0];
#pragma unroll
    for (int w = 1; w < 8; w++) tot2 += red[w];
    const float var = tot2 * (1.0f / DMODEL);
    const float inv = rsqrtf(var + 1e-6f);

    const int c = tid * 4;
    float* __restrict__ orow = out + (size_t)row * DMODEL;
    orow[c + 0] = d0 * inv * gamma[c + 0] + beta[c + 0];
    orow[c + 1] = d1 * inv * gamma[c + 1] + beta[c + 1];
    orow[c + 2] = d2 * inv * gamma[c + 2] + beta[c + 2];
    orow[c + 3] = d3 * inv * gamma[c + 3] + beta[c + 3];
}

// =========================================================================
extern "C" void kernel_launch(void* const* d_in, const int* in_sizes, int n_in,
                              void* d_out, int out_size)
{
    const float* X     = (const float*)d_in[0];
    const int*   mask  = (const int*)d_in[1];
    const float* Wq    = (const float*)d_in[2];
    const float* Wk    = (const float*)d_in[3];
    const float* Wv    = (const float*)d_in[4];
    const float* Wo    = (const float*)d_in[5];
    const float* gamma = (const float*)d_in[6];
    const float* beta  = (const float*)d_in[7];
    float* out = (float*)d_out;

    const long long LN_N   = (long long)BB * LLEN * DMODEL;
    const long long ATTN_N = (long long)BB * NH * LLEN * LLEN;
    float* attn_ptr = ((long long)out_size >= LN_N + ATTN_N) ? (out + LN_N) : nullptr;

    cudaFuncSetAttribute(qkv_mma_kernel,
                         cudaFuncAttributeMaxDynamicSharedMemorySize, QKV_SMEM_BYTES);
    cudaFuncSetAttribute(fused_attn_kernel,
                         cudaFuncAttributeMaxDynamicSharedMemorySize, ATTN_SMEM_BYTES);
    cudaFuncSetAttribute(proj_mma_kernel,
                         cudaFuncAttributeMaxDynamicSharedMemorySize, QKV_SMEM_BYTES);

    prep_wo_kernel<<<512, 256>>>(Wo);
    qkv_mma_kernel<<<dim3(24, 64), 256, QKV_SMEM_BYTES>>>(X, Wq, Wk, Wv);
    fused_attn_kernel<<<dim3(64, BB * NH), 256, ATTN_SMEM_BYTES>>>(mask, attn_ptr);
    pv_mma_kernel<<<dim3(8, BB * NH), 256>>>(attn_ptr);
    proj_mma_kernel<<<dim3(8, 64), 256, QKV_SMEM_BYTES>>>();
    ln_kernel<<<BB * LLEN, 256>>>(X, gamma, beta, out);
}